// round 1
// baseline (speedup 1.0000x reference)
#include <cuda_runtime.h>
#include <cstdint>

// Problem dims
#define KT 32768
#define MT 2048
#define NT 256

// GEMM tiling
#define SPLITS 16
#define KCH (KT / SPLITS)     // 2048 per split
#define BM 128
#define BN 128
#define BK 16
#define NITER (KCH / BK)      // 128
#define A_PITCH 20            // 16 + 4 pad -> conflict-free A fragment LDS
#define B_PITCH 136           // 128 + 8 pad -> conflict-free B fragment LDS

// Scratch (allowed: __device__ globals, no runtime allocation)
__device__ float g_W[KT * NT];                 // 32 MB, tf32-rounded W (row-major [K][N])
__device__ float g_part[SPLITS * MT * NT];     // 32 MB, split-K partials

__device__ __forceinline__ uint32_t f2tf32(float x) {
    uint32_t u;
    asm("cvt.rna.tf32.f32 %0, %1;" : "=r"(u) : "f"(x));
    return u;
}

// ---------------------------------------------------------------------------
// Kernel 1: W[k][r] = U2[i2][r] * U1[i1][r] * U0[i0][r], k = i2*1024+i1*32+i0
// Stored pre-rounded to tf32 so the GEMM consumes it with zero conversions.
// ---------------------------------------------------------------------------
__global__ void build_w_kernel(const float* __restrict__ U0,
                               const float* __restrict__ U1,
                               const float* __restrict__ U2) {
    const int k = blockIdx.x;        // 0..32767
    const int r = threadIdx.x;       // 0..255
    const int i0 = k & 31;
    const int i1 = (k >> 5) & 31;
    const int i2 = k >> 10;
    const float w = U2[i2 * NT + r] * U1[i1 * NT + r] * U0[i0 * NT + r];
    g_W[k * NT + r] = __uint_as_float(f2tf32(w));
}

// ---------------------------------------------------------------------------
// Kernel 2: split-K TF32 tensor-core GEMM. partials[z] = x[:, zK:(z+1)K] @ W[zK:(z+1)K, :]
// ---------------------------------------------------------------------------
__device__ __forceinline__ void mma_tf32(float* c, const uint32_t* a, const uint32_t* b) {
    asm volatile(
        "mma.sync.aligned.m16n8k8.row.col.f32.tf32.tf32.f32 "
        "{%0,%1,%2,%3}, {%4,%5,%6,%7}, {%8,%9}, {%0,%1,%2,%3};"
        : "+f"(c[0]), "+f"(c[1]), "+f"(c[2]), "+f"(c[3])
        : "r"(a[0]), "r"(a[1]), "r"(a[2]), "r"(a[3]), "r"(b[0]), "r"(b[1]));
}

__global__ __launch_bounds__(256, 2) void gemm_kernel(const float* __restrict__ x) {
    __shared__ float As[2][BM][A_PITCH];
    __shared__ float Bs[2][BK][B_PITCH];

    const int t  = threadIdx.x;
    const int n0 = blockIdx.x * BN;
    const int m0 = blockIdx.y * BM;
    const int z  = blockIdx.z;
    const int k0 = z * KCH;

    const int lane = t & 31;
    const int warp = t >> 5;
    const int wm = (warp & 3) * 32;   // 4 warps along M (32 rows each)
    const int wn = (warp >> 2) * 64;  // 2 warps along N (64 cols each)
    const int g  = lane >> 2;         // groupID
    const int tg = lane & 3;          // threadID-in-group

    // Global staging addresses (each thread: 2 float4 of A, 2 float4 of B per tile)
    const float* ax = x + (long)(m0 + (t >> 2)) * KT + k0 + (t & 3) * 4;
    const float* bw = g_W + (long)(k0 + (t >> 5)) * NT + n0 + (t & 31) * 4;

    // SMEM staging addresses
    const int a_m = t >> 2;          // 0..63 (+64 for second half)
    const int a_k = (t & 3) * 4;     // 0,4,8,12
    const int b_k = t >> 5;          // 0..7  (+8 for second half)
    const int b_n = (t & 31) * 4;    // 0..124

    float acc[2][8][4];
#pragma unroll
    for (int mf = 0; mf < 2; mf++)
#pragma unroll
        for (int nf = 0; nf < 8; nf++)
#pragma unroll
            for (int i = 0; i < 4; i++) acc[mf][nf][i] = 0.0f;

    // Prologue: load tile 0 into buffer 0
    {
        float4 ra0 = *(const float4*)(ax);
        float4 ra1 = *(const float4*)(ax + 64 * KT);
        float4 rb0 = *(const float4*)(bw);
        float4 rb1 = *(const float4*)(bw + 8 * NT);
        ax += BK;
        bw += (long)BK * NT;
        float4 ta0, ta1;
        ta0.x = __uint_as_float(f2tf32(ra0.x)); ta0.y = __uint_as_float(f2tf32(ra0.y));
        ta0.z = __uint_as_float(f2tf32(ra0.z)); ta0.w = __uint_as_float(f2tf32(ra0.w));
        ta1.x = __uint_as_float(f2tf32(ra1.x)); ta1.y = __uint_as_float(f2tf32(ra1.y));
        ta1.z = __uint_as_float(f2tf32(ra1.z)); ta1.w = __uint_as_float(f2tf32(ra1.w));
        *(float4*)&As[0][a_m][a_k]      = ta0;
        *(float4*)&As[0][a_m + 64][a_k] = ta1;
        *(float4*)&Bs[0][b_k][b_n]      = rb0;   // W already tf32-rounded
        *(float4*)&Bs[0][b_k + 8][b_n]  = rb1;
    }
    __syncthreads();

    int buf = 0;
    for (int it = 0; it < NITER; it++) {
        const bool pf = (it + 1 < NITER);
        float4 na0, na1, nb0, nb1;
        if (pf) {
            na0 = *(const float4*)(ax);
            na1 = *(const float4*)(ax + 64 * KT);
            nb0 = *(const float4*)(bw);
            nb1 = *(const float4*)(bw + 8 * NT);
            ax += BK;
            bw += (long)BK * NT;
        }

#pragma unroll
        for (int ks = 0; ks < 2; ks++) {
            const int kb = ks * 8;
            uint32_t a[2][4];
#pragma unroll
            for (int mf = 0; mf < 2; mf++) {
                const int mr = wm + mf * 16 + g;
                a[mf][0] = __float_as_uint(As[buf][mr][kb + tg]);
                a[mf][1] = __float_as_uint(As[buf][mr + 8][kb + tg]);
                a[mf][2] = __float_as_uint(As[buf][mr][kb + tg + 4]);
                a[mf][3] = __float_as_uint(As[buf][mr + 8][kb + tg + 4]);
            }
            uint32_t b[8][2];
#pragma unroll
            for (int nf = 0; nf < 8; nf++) {
                const int nc = wn + nf * 8 + g;
                b[nf][0] = __float_as_uint(Bs[buf][kb + tg][nc]);
                b[nf][1] = __float_as_uint(Bs[buf][kb + tg + 4][nc]);
            }
#pragma unroll
            for (int mf = 0; mf < 2; mf++)
#pragma unroll
                for (int nf = 0; nf < 8; nf++)
                    mma_tf32(acc[mf][nf], a[mf], b[nf]);
        }

        if (pf) {
            const int nb = buf ^ 1;
            float4 ta0, ta1;
            ta0.x = __uint_as_float(f2tf32(na0.x)); ta0.y = __uint_as_float(f2tf32(na0.y));
            ta0.z = __uint_as_float(f2tf32(na0.z)); ta0.w = __uint_as_float(f2tf32(na0.w));
            ta1.x = __uint_as_float(f2tf32(na1.x)); ta1.y = __uint_as_float(f2tf32(na1.y));
            ta1.z = __uint_as_float(f2tf32(na1.z)); ta1.w = __uint_as_float(f2tf32(na1.w));
            *(float4*)&As[nb][a_m][a_k]      = ta0;
            *(float4*)&As[nb][a_m + 64][a_k] = ta1;
            *(float4*)&Bs[nb][b_k][b_n]      = nb0;
            *(float4*)&Bs[nb][b_k + 8][b_n]  = nb1;
        }
        __syncthreads();
        buf ^= 1;
    }

    // Epilogue: write this split's partial tile
    float* part = g_part + (long)z * MT * NT;
#pragma unroll
    for (int mf = 0; mf < 2; mf++) {
        const int mr = m0 + wm + mf * 16 + g;
#pragma unroll
        for (int nf = 0; nf < 8; nf++) {
            const int nc = n0 + wn + nf * 8 + tg * 2;
            float2 v0, v1;
            v0.x = acc[mf][nf][0]; v0.y = acc[mf][nf][1];
            v1.x = acc[mf][nf][2]; v1.y = acc[mf][nf][3];
            *(float2*)&part[(long)mr * NT + nc]       = v0;
            *(float2*)&part[(long)(mr + 8) * NT + nc] = v1;
        }
    }
}

// ---------------------------------------------------------------------------
// Kernel 3: deterministic split-K reduction -> d_out (writes every element)
// ---------------------------------------------------------------------------
__global__ void reduce_kernel(float* __restrict__ out) {
    const int i = blockIdx.x * blockDim.x + threadIdx.x;   // over MT*NT/4 float4s
    const float4* p = (const float4*)g_part;
    float4 s = p[i];
#pragma unroll
    for (int zz = 1; zz < SPLITS; zz++) {
        const float4 v = p[(long)zz * (MT * NT / 4) + i];
        s.x += v.x; s.y += v.y; s.z += v.z; s.w += v.w;
    }
    ((float4*)out)[i] = s;
}

// ---------------------------------------------------------------------------
extern "C" void kernel_launch(void* const* d_in, const int* in_sizes, int n_in,
                              void* d_out, int out_size) {
    const float* x  = (const float*)d_in[0];
    const float* U0 = (const float*)d_in[1];
    const float* U1 = (const float*)d_in[2];
    const float* U2 = (const float*)d_in[3];
    float* out = (float*)d_out;

    build_w_kernel<<<KT, NT>>>(U0, U1, U2);

    dim3 grid(NT / BN, MT / BM, SPLITS);   // (2, 16, 16) = 512 CTAs
    gemm_kernel<<<grid, 256>>>(x);

    reduce_kernel<<<(MT * NT / 4) / 256, 256>>>(out);
}

// round 4
// speedup vs baseline: 1.0199x; 1.0199x over previous
#include <cuda_runtime.h>
#include <cstdint>

// ---------------------------------------------------------------------------
// out[2048,256] = x[2048,32768] @ W[32768,256],
// W[k,r] = U2[i2,r]*U1[i1,r]*U0[i0,r], k = i2*1024 + i1*32 + i0.
//
// sm_103 (non-'a' PTX target): tcgen05 unavailable -> Ampere-style mma.sync
// tf32 GEMM. B (W) is never materialized: B fragments are computed in
// registers from a 64-reg U0 cache times a per-stage p12 scalar.
// A streams through a 4-deep cp.async smem pipeline (conflict-free pitch 36).
// ---------------------------------------------------------------------------

#define KT 32768
#define MT 2048
#define NT 256

#define SPLITS 4
#define KCH (KT / SPLITS)       // 8192
#define BK 32                   // one i0 period per stage (i1,i2 fixed)
#define NS (KCH / BK)           // 256 stages
#define BM 128
#define BN 128
#define APITCH 36               // floats per A row: 32 + 4 pad -> conflict-free LDS
#define A_BYTES (BM * APITCH * 4)   // 18432 B per stage
#define NBUF 4
#define SMEM_TOTAL (NBUF * A_BYTES) // 73728 B

__device__ float g_part[SPLITS * MT * NT];   // 8 MB split-K partials

__device__ __forceinline__ float t32(float x) {
    uint32_t u;
    asm("cvt.rna.tf32.f32 %0, %1;" : "=r"(u) : "f"(x));
    return __uint_as_float(u);
}
__device__ __forceinline__ uint32_t smem_u32(const void* p) {
    uint32_t a;
    asm("{ .reg .u64 t; cvta.to.shared.u64 t, %1; cvt.u32.u64 %0, t; }" : "=r"(a) : "l"(p));
    return a;
}
__device__ __forceinline__ void cp16(uint32_t dst, const void* src) {
    asm volatile("cp.async.cg.shared.global [%0], [%1], 16;" :: "r"(dst), "l"(src) : "memory");
}
__device__ __forceinline__ void mma_tf32(float* c, const uint32_t* a, const uint32_t* b) {
    asm volatile(
        "mma.sync.aligned.m16n8k8.row.col.f32.tf32.tf32.f32 "
        "{%0,%1,%2,%3}, {%4,%5,%6,%7}, {%8,%9}, {%0,%1,%2,%3};"
        : "+f"(c[0]), "+f"(c[1]), "+f"(c[2]), "+f"(c[3])
        : "r"(a[0]), "r"(a[1]), "r"(a[2]), "r"(a[3]), "r"(b[0]), "r"(b[1]));
}

// ---------------------------------------------------------------------------
__global__ __launch_bounds__(256, 1) void gemm_kernel(
    const float* __restrict__ x, const float* __restrict__ U0,
    const float* __restrict__ U1, const float* __restrict__ U2) {
    extern __shared__ float As[];            // [NBUF][BM][APITCH]
    const uint32_t sbase = smem_u32(As);

    const int tid  = threadIdx.x;
    const int lane = tid & 31;
    const int w    = tid >> 5;
    const int g    = lane >> 2;              // 0..7
    const int tg   = lane & 3;               // 0..3
    const int wm   = (w & 3) * 32;           // 4 warps along M (32 rows each)
    const int wn   = (w >> 2) * 64;          // 2 warps along N (64 cols each)
    const int m0   = blockIdx.x * BM;
    const int n0   = blockIdx.y * BN;
    const int z    = blockIdx.z;
    const long k0  = (long)z * KCH;

    // ---- register caches for the B operand ----
    // u0c[nf][j] = tf32(U0[i0 = tg+4j, nc]),  nc = n0 + wn + nf*8 + g
    float u0c[8][8];
    float p12[8], u1n[8], u2n[8];
#pragma unroll
    for (int nf = 0; nf < 8; nf++) {
        const int nc = n0 + wn + nf * 8 + g;
#pragma unroll
        for (int j = 0; j < 8; j++)
            u0c[nf][j] = t32(U0[(tg + 4 * j) * NT + nc]);
        // p12 for stage 0: i2 = z*8, i1 = 0
        p12[nf] = t32(t32(U2[(z * 8) * NT + nc]) * t32(U1[nc]));
    }

    // ---- A producer mapping: 4x 16B chunks per thread per stage ----
    // chunk cid = tid + 256*j : row = cid>>3 (0..127), kc = cid&7 (0..7)

    // prologue: stages 0..2
#pragma unroll
    for (int p = 0; p < 3; p++) {
#pragma unroll
        for (int j = 0; j < 4; j++) {
            const int cid = tid + 256 * j;
            const int row = cid >> 3, kc = cid & 7;
            cp16(sbase + (uint32_t)(p * BM + row) * (APITCH * 4) + kc * 16,
                 x + (long)(m0 + row) * KT + k0 + p * BK + kc * 4);
        }
        asm volatile("cp.async.commit_group;" ::: "memory");
    }

    float acc[2][8][4];
#pragma unroll
    for (int mf = 0; mf < 2; mf++)
#pragma unroll
        for (int nf = 0; nf < 8; nf++)
#pragma unroll
            for (int i = 0; i < 4; i++) acc[mf][nf][i] = 0.0f;

    for (int s = 0; s < NS; s++) {
        asm volatile("cp.async.wait_group 2;" ::: "memory");
        __syncthreads();

        // prefetch stage s+3 into slot (s+3)&3 (read last at iter s-1: safe)
        if (s + 3 < NS) {
            const int slot = (s + 3) & 3;
#pragma unroll
            for (int j = 0; j < 4; j++) {
                const int cid = tid + 256 * j;
                const int row = cid >> 3, kc = cid & 7;
                cp16(sbase + (uint32_t)(slot * BM + row) * (APITCH * 4) + kc * 16,
                     x + (long)(m0 + row) * KT + k0 + (s + 3) * BK + kc * 4);
            }
        }
        asm volatile("cp.async.commit_group;" ::: "memory");

        // issue next-stage p12 loads early (L1-resident U1/U2)
        if (s + 1 < NS) {
            const int i1 = (s + 1) & 31;
            const int i2 = z * 8 + ((s + 1) >> 5);
#pragma unroll
            for (int nf = 0; nf < 8; nf++) {
                const int nc = n0 + wn + nf * 8 + g;
                u2n[nf] = U2[i2 * NT + nc];
                u1n[nf] = U1[i1 * NT + nc];
            }
        }

        const float* ab = As + (s & 3) * BM * APITCH;
#pragma unroll
        for (int ks = 0; ks < 4; ks++) {
            const int kb = ks * 8;
            uint32_t a[2][4];
#pragma unroll
            for (int mf = 0; mf < 2; mf++) {
                const int mr = wm + mf * 16 + g;
                a[mf][0] = __float_as_uint(ab[mr * APITCH + kb + tg]);
                a[mf][1] = __float_as_uint(ab[(mr + 8) * APITCH + kb + tg]);
                a[mf][2] = __float_as_uint(ab[mr * APITCH + kb + tg + 4]);
                a[mf][3] = __float_as_uint(ab[(mr + 8) * APITCH + kb + tg + 4]);
            }
#pragma unroll
            for (int nf = 0; nf < 8; nf++) {
                uint32_t b[2];
                b[0] = __float_as_uint(t32(p12[nf] * u0c[nf][2 * ks]));
                b[1] = __float_as_uint(t32(p12[nf] * u0c[nf][2 * ks + 1]));
                mma_tf32(acc[0][nf], a[0], b);
                mma_tf32(acc[1][nf], a[1], b);
            }
        }

        if (s + 1 < NS) {
#pragma unroll
            for (int nf = 0; nf < 8; nf++)
                p12[nf] = t32(t32(u2n[nf]) * t32(u1n[nf]));
        }
    }

    // ---- epilogue: write split partials ----
    float* part = g_part + (long)z * MT * NT;
#pragma unroll
    for (int mf = 0; mf < 2; mf++) {
        const int mr = m0 + wm + mf * 16 + g;
#pragma unroll
        for (int nf = 0; nf < 8; nf++) {
            const int nc = n0 + wn + nf * 8 + tg * 2;
            float2 v0, v1;
            v0.x = acc[mf][nf][0]; v0.y = acc[mf][nf][1];
            v1.x = acc[mf][nf][2]; v1.y = acc[mf][nf][3];
            *(float2*)&part[(long)mr * NT + nc]       = v0;
            *(float2*)&part[(long)(mr + 8) * NT + nc] = v1;
        }
    }
}

// ---------------------------------------------------------------------------
__global__ void reduce_kernel(float* __restrict__ out) {
    const int i = blockIdx.x * blockDim.x + threadIdx.x;   // over MT*NT/4 float4s
    const float4* p = (const float4*)g_part;
    float4 s = p[i];
#pragma unroll
    for (int z = 1; z < SPLITS; z++) {
        const float4 v = p[(long)z * (MT * NT / 4) + i];
        s.x += v.x; s.y += v.y; s.z += v.z; s.w += v.w;
    }
    ((float4*)out)[i] = s;
}

// ---------------------------------------------------------------------------
extern "C" void kernel_launch(void* const* d_in, const int* in_sizes, int n_in,
                              void* d_out, int out_size) {
    const float* x  = (const float*)d_in[0];
    const float* U0 = (const float*)d_in[1];
    const float* U1 = (const float*)d_in[2];
    const float* U2 = (const float*)d_in[3];
    float* out = (float*)d_out;

    static int smem_set = 0;
    if (!smem_set) {
        cudaFuncSetAttribute(gemm_kernel, cudaFuncAttributeMaxDynamicSharedMemorySize,
                             SMEM_TOTAL);
        smem_set = 1;
    }

    dim3 grid(MT / BM, NT / BN, SPLITS);   // (16, 2, 4) = 128 CTAs
    gemm_kernel<<<grid, 256, SMEM_TOTAL>>>(x, U0, U1, U2);

    reduce_kernel<<<(MT * NT / 4) / 256, 256>>>(out);
}

// round 5
// speedup vs baseline: 1.0950x; 1.0736x over previous
#include <cuda_runtime.h>
#include <cuda_fp16.h>
#include <cstdint>

// ---------------------------------------------------------------------------
// out[2048,256] = x[2048,32768] @ W[32768,256],
// W[k,r] = U2[i2,r]*U1[i1,r]*U0[i0,r], k = i2*1024 + i1*32 + i0.
//
// Single-limb fp16 mma.sync.m16n8k16 GEMM (fp32 accumulate).
// fp16 mantissa (10 bits) == tf32 mantissa -> same accuracy class, but
// 2048 MAC/HMMA instruction vs 1024 for tf32 -> half the HMMA count.
// W is never materialized: B fragments computed in registers from a fp32
// U0 column cache, single fp32->fp16 rounding at pack time.
// A: LDG fp32 -> fp16 convert -> swizzled STS, 3-slot smem ring.
// Split-K reduction fused via per-tile arrival counters (single kernel).
// ---------------------------------------------------------------------------

#define KT 32768
#define MT 2048
#define NT 256

#define SPLITS 4
#define KCH (KT / SPLITS)       // 8192
#define BK 64                   // 64 k per stage = 128 B fp16 per A row
#define NS (KCH / BK)           // 128 stages
#define BM 128
#define BN 128

#define SLOT_BYTES (BM * 128)   // 16 KB per stage
#define NSLOT 3
#define SMEM_BYTES (NSLOT * SLOT_BYTES)   // 48 KB

__device__ float g_part[SPLITS * MT * NT];        // 8 MB split-K partials
__device__ int   g_cnt[(MT / BM) * (NT / BN)];    // 32 tile counters (zero-init)

__device__ __forceinline__ uint32_t smem_u32(const void* p) {
    uint32_t a;
    asm("{ .reg .u64 t; cvta.to.shared.u64 t, %1; cvt.u32.u64 %0, t; }" : "=r"(a) : "l"(p));
    return a;
}
__device__ __forceinline__ uint32_t pkh2(float lo, float hi) {
    __half2 h = __floats2half2_rn(lo, hi);           // .x = lo (low 16 bits)
    return *reinterpret_cast<uint32_t*>(&h);
}
__device__ __forceinline__ void ldm4(uint32_t* r, uint32_t addr) {
    asm volatile("ldmatrix.sync.aligned.m8n8.x4.shared.b16 {%0,%1,%2,%3}, [%4];"
                 : "=r"(r[0]), "=r"(r[1]), "=r"(r[2]), "=r"(r[3]) : "r"(addr));
}
__device__ __forceinline__ void mma16816(float* c, const uint32_t* a, uint32_t b0, uint32_t b1) {
    asm volatile(
        "mma.sync.aligned.m16n8k16.row.col.f32.f16.f16.f32 "
        "{%0,%1,%2,%3},{%4,%5,%6,%7},{%8,%9},{%0,%1,%2,%3};"
        : "+f"(c[0]), "+f"(c[1]), "+f"(c[2]), "+f"(c[3])
        : "r"(a[0]), "r"(a[1]), "r"(a[2]), "r"(a[3]), "r"(b0), "r"(b1));
}

// ---------------------------------------------------------------------------
__global__ __launch_bounds__(256, 1) void gemm_kernel(
    const float* __restrict__ x, const float* __restrict__ U0,
    const float* __restrict__ U1, const float* __restrict__ U2,
    float* __restrict__ out) {
    extern __shared__ char smem[];
    const uint32_t sb = smem_u32(smem);
    __shared__ int s_flag;

    const int tid  = threadIdx.x;
    const int lane = tid & 31;
    const int w    = tid >> 5;
    const int g    = lane >> 2;        // 0..7
    const int tg   = lane & 3;         // 0..3
    const int wm   = (w & 3) * 32;     // 4 warps along M
    const int wn   = (w >> 2) * 64;    // 2 warps along N
    const int m0   = blockIdx.x * BM;
    const int n0   = blockIdx.y * BN;
    const int z    = blockIdx.z;
    const long k0  = (long)z * KCH;

    // ---- fp32 U0 column cache: B fragment sources (i0 layout of m16n8k16) ----
    // u0c[nf][h*4+q]: i0 = h*16 + {2tg, 2tg+1, 2tg+8, 2tg+9}
    float u0c[8][8];
#pragma unroll
    for (int nf = 0; nf < 8; nf++) {
        const int nc = n0 + wn + nf * 8 + g;
#pragma unroll
        for (int h = 0; h < 2; h++) {
            u0c[nf][h * 4 + 0] = U0[(h * 16 + 2 * tg)     * NT + nc];
            u0c[nf][h * 4 + 1] = U0[(h * 16 + 2 * tg + 1) * NT + nc];
            u0c[nf][h * 4 + 2] = U0[(h * 16 + 2 * tg + 8) * NT + nc];
            u0c[nf][h * 4 + 3] = U0[(h * 16 + 2 * tg + 9) * NT + nc];
        }
    }

    // ---- A producer mapping: thread -> (row, k-half of 32) ----
    const int prow = tid & 127;
    const int pkh  = tid >> 7;                 // 0/1
    const float* gx = x + (long)(m0 + prow) * KT + k0 + pkh * 32;
    uint32_t sts_off[4];
#pragma unroll
    for (int cc = 0; cc < 4; cc++) {
        const int c = 4 * pkh + cc;            // chunk = k octet 0..7
        sts_off[cc] = (uint32_t)prow * 128 + (uint32_t)((c ^ (prow & 7)) << 4);
    }

    // ---- A consumer (ldmatrix) per-lane addressing ----
    const int ltile = lane >> 3, lr = lane & 7;
    const uint32_t lrow0 = (uint32_t)(wm + (ltile & 1) * 8 + lr) * 128;
    const uint32_t lrow1 = lrow0 + 16 * 128;
    const int lcoff = ltile >> 1;

    // ---- prologue: stage 0 -> slot 0; xr <- stage 1 ----
    float4 xr[8];
#pragma unroll
    for (int q = 0; q < 8; q++) xr[q] = *(const float4*)(gx + q * 4);
    {
        char* s0 = smem;
#pragma unroll
        for (int cc = 0; cc < 4; cc++) {
            uint4 v;
            v.x = pkh2(xr[2 * cc].x, xr[2 * cc].y);
            v.y = pkh2(xr[2 * cc].z, xr[2 * cc].w);
            v.z = pkh2(xr[2 * cc + 1].x, xr[2 * cc + 1].y);
            v.w = pkh2(xr[2 * cc + 1].z, xr[2 * cc + 1].w);
            *(uint4*)(s0 + sts_off[cc]) = v;
        }
    }
#pragma unroll
    for (int q = 0; q < 8; q++) xr[q] = *(const float4*)(gx + BK + q * 4);
    __syncthreads();

    float acc[2][8][4];
#pragma unroll
    for (int mf = 0; mf < 2; mf++)
#pragma unroll
        for (int nf = 0; nf < 8; nf++)
#pragma unroll
            for (int i = 0; i < 4; i++) acc[mf][nf][i] = 0.0f;

    for (int s = 0; s < NS; s++) {
        // store stage s+1 (regs -> slot (s+1)%3); safe vs readers of slots s, s-1
        if (s + 1 < NS) {
            char* sd = smem + ((s + 1) % 3) * SLOT_BYTES;
#pragma unroll
            for (int cc = 0; cc < 4; cc++) {
                uint4 v;
                v.x = pkh2(xr[2 * cc].x, xr[2 * cc].y);
                v.y = pkh2(xr[2 * cc].z, xr[2 * cc].w);
                v.z = pkh2(xr[2 * cc + 1].x, xr[2 * cc + 1].y);
                v.w = pkh2(xr[2 * cc + 1].z, xr[2 * cc + 1].w);
                *(uint4*)(sd + sts_off[cc]) = v;
            }
        }
        // load stage s+2 into regs (latency covered by this stage's MMAs)
        if (s + 2 < NS) {
            const float* gs = gx + (long)(s + 2) * BK;
#pragma unroll
            for (int q = 0; q < 8; q++) xr[q] = *(const float4*)(gs + q * 4);
        }

        // per-stage W scalars: stage covers two i1 values (k 0-31 / 32-63)
        const int i1a = (2 * s) & 31;
        const int i1b = (2 * s + 1) & 31;
        const int i2  = z * (KCH / 1024) + (s >> 4);
        float p12a[8], p12b[8];
#pragma unroll
        for (int nf = 0; nf < 8; nf++) {
            const int nc = n0 + wn + nf * 8 + g;
            const float u2v = U2[i2 * NT + nc];
            p12a[nf] = u2v * U1[i1a * NT + nc];
            p12b[nf] = u2v * U1[i1b * NT + nc];
        }

        __syncthreads();   // slot s fully written (last iter); A ready

        const uint32_t slotb = sb + (s % 3) * SLOT_BYTES;
#pragma unroll
        for (int ks = 0; ks < 4; ks++) {       // 4 x k16 per stage
            uint32_t a0[4], a1[4];
            const uint32_t csw = (uint32_t)(((ks * 2 + lcoff) ^ lr) << 4);
            ldm4(a0, slotb + lrow0 + csw);
            ldm4(a1, slotb + lrow1 + csw);
            const int q = (ks & 1) * 4;        // i0 repeats with period 32
#pragma unroll
            for (int nf = 0; nf < 8; nf++) {
                const float p = (ks < 2) ? p12a[nf] : p12b[nf];
                const uint32_t b0 = pkh2(p * u0c[nf][q + 0], p * u0c[nf][q + 1]);
                const uint32_t b1 = pkh2(p * u0c[nf][q + 2], p * u0c[nf][q + 3]);
                mma16816(acc[0][nf], a0, b0, b1);
                mma16816(acc[1][nf], a1, b0, b1);
            }
        }
    }

    // ---- write split partials ----
    float* part = g_part + (long)z * MT * NT;
#pragma unroll
    for (int mf = 0; mf < 2; mf++) {
        const int mr = m0 + wm + mf * 16 + g;
#pragma unroll
        for (int nf = 0; nf < 8; nf++) {
            const int nc = n0 + wn + nf * 8 + tg * 2;
            float2 v0, v1;
            v0.x = acc[mf][nf][0]; v0.y = acc[mf][nf][1];
            v1.x = acc[mf][nf][2]; v1.y = acc[mf][nf][3];
            *(float2*)&part[(long)mr * NT + nc]       = v0;
            *(float2*)&part[(long)(mr + 8) * NT + nc] = v1;
        }
    }

    // ---- fused split-K reduction: last CTA per (m,n) tile sums partials ----
    __threadfence();
    __syncthreads();
    if (tid == 0) {
        const int tile = blockIdx.x * (NT / BN) + blockIdx.y;
        const int old = atomicAdd(&g_cnt[tile], 1);
        s_flag = (old == SPLITS - 1);
        if (s_flag) g_cnt[tile] = 0;           // reset for next graph replay
    }
    __syncthreads();
    if (s_flag) {
        __threadfence();
#pragma unroll
        for (int j = 0; j < (BM * BN / 4) / 256; j++) {   // 16 float4 per thread
            const int f   = tid + 256 * j;
            const int row = f >> 5;
            const int c4  = f & 31;
            const long off = (long)(m0 + row) * NT + n0 + c4 * 4;
            float4 sum = *(const float4*)(g_part + off);
#pragma unroll
            for (int zz = 1; zz < SPLITS; zz++) {
                const float4 v = *(const float4*)(g_part + (long)zz * MT * NT + off);
                sum.x += v.x; sum.y += v.y; sum.z += v.z; sum.w += v.w;
            }
            *(float4*)(out + off) = sum;
        }
    }
}

// ---------------------------------------------------------------------------
extern "C" void kernel_launch(void* const* d_in, const int* in_sizes, int n_in,
                              void* d_out, int out_size) {
    const float* x  = (const float*)d_in[0];
    const float* U0 = (const float*)d_in[1];
    const float* U1 = (const float*)d_in[2];
    const float* U2 = (const float*)d_in[3];
    float* out = (float*)d_out;

    static int smem_set = 0;
    if (!smem_set) {
        cudaFuncSetAttribute(gemm_kernel, cudaFuncAttributeMaxDynamicSharedMemorySize,
                             SMEM_BYTES);
        smem_set = 1;
    }

    dim3 grid(MT / BM, NT / BN, SPLITS);   // (16, 2, 4) = 128 CTAs
    gemm_kernel<<<grid, 256, SMEM_BYTES>>>(x, U0, U1, U2, out);
}

// round 9
// speedup vs baseline: 1.1567x; 1.0564x over previous
#include <cuda_runtime.h>
#include <cuda_fp16.h>
#include <cstdint>

// ---------------------------------------------------------------------------
// out[2048,256] = x[2048,32768] @ W[32768,256],
// W[k,r] = U2[i2,r]*U1[i1,r]*U0[i0,r], k = i2*1024 + i1*32 + i0.
//
// fp16 m16n8k16 mma.sync, fp32 accumulate. W never materialized (register
// compute from half2 U0 cache). Restructured for occupancy: BN=64, warp tile
// 32x32, <=128 regs -> 2 CTAs/SM (16 warps/SM), 256 CTAs single wave.
// A: LDG fp32 -> half2 pack -> STS (pitch-80 rows, conflict-free ldmatrix).
// Fused split-K reduction via per-tile arrival counters.
// ---------------------------------------------------------------------------

#define KT 32768
#define MT 2048
#define NT 256

#define SPLITS 4
#define KCH (KT / SPLITS)        // 8192
#define BK 32                    // one i0 period per stage
#define NS (KCH / BK)            // 256 stages
#define BM 128
#define BN 64

#define PITCH 80                 // bytes per A row (64 data + 16 pad)
#define SLOT_BYTES (BM * PITCH)  // 10240
#define SMEM_BYTES (3 * SLOT_BYTES)

__device__ float g_part[SPLITS * MT * NT];        // 8 MB split-K partials
__device__ int   g_cnt[(MT / BM) * (NT / BN)];    // 64 tile counters

__device__ __forceinline__ uint32_t smem_u32(const void* p) {
    uint32_t a;
    asm("{ .reg .u64 t; cvta.to.shared.u64 t, %1; cvt.u32.u64 %0, t; }" : "=r"(a) : "l"(p));
    return a;
}
__device__ __forceinline__ uint32_t pkh2(float lo, float hi) {
    __half2 h = __floats2half2_rn(lo, hi);
    return *reinterpret_cast<uint32_t*>(&h);
}
__device__ __forceinline__ uint32_t hm2(uint32_t a, uint32_t b) {
    __half2 r = __hmul2(*reinterpret_cast<__half2*>(&a), *reinterpret_cast<__half2*>(&b));
    return *reinterpret_cast<uint32_t*>(&r);
}
__device__ __forceinline__ void ldm4(uint32_t* r, uint32_t addr) {
    asm volatile("ldmatrix.sync.aligned.m8n8.x4.shared.b16 {%0,%1,%2,%3}, [%4];"
                 : "=r"(r[0]), "=r"(r[1]), "=r"(r[2]), "=r"(r[3]) : "r"(addr));
}
__device__ __forceinline__ void mma16816(float* c, const uint32_t* a, uint32_t b0, uint32_t b1) {
    asm volatile(
        "mma.sync.aligned.m16n8k16.row.col.f32.f16.f16.f32 "
        "{%0,%1,%2,%3},{%4,%5,%6,%7},{%8,%9},{%0,%1,%2,%3};"
        : "+f"(c[0]), "+f"(c[1]), "+f"(c[2]), "+f"(c[3])
        : "r"(a[0]), "r"(a[1]), "r"(a[2]), "r"(a[3]), "r"(b0), "r"(b1));
}

// ---------------------------------------------------------------------------
__global__ __launch_bounds__(256, 2) void gemm_kernel(
    const float* __restrict__ x, const float* __restrict__ U0,
    const float* __restrict__ U1, const float* __restrict__ U2,
    float* __restrict__ out) {
    extern __shared__ char smem[];
    const uint32_t sb = smem_u32(smem);
    __shared__ int s_flag;

    const int tid  = threadIdx.x;
    const int lane = tid & 31;
    const int w    = tid >> 5;
    const int g    = lane >> 2;          // 0..7
    const int tg   = lane & 3;           // 0..3
    const int wm   = (w & 3) * 32;       // 4 warps along M
    const int wn   = (w >> 2) * 32;      // 2 warps along N (32 cols each)
    const int m0   = blockIdx.x * BM;
    const int n0   = blockIdx.y * BN;
    const int z    = blockIdx.z;
    const long k0  = (long)z * KCH;

    // ---- half2 U0 cache: u0h[nf][ks][h] covers i0 = ks*16 + 2tg + 8h + {0,1}
    uint32_t u0h[4][2][2];
#pragma unroll
    for (int nf = 0; nf < 4; nf++) {
        const int nc = n0 + wn + nf * 8 + g;
#pragma unroll
        for (int ks = 0; ks < 2; ks++)
#pragma unroll
            for (int h = 0; h < 2; h++) {
                const int i0 = ks * 16 + 2 * tg + 8 * h;
                u0h[nf][ks][h] = pkh2(U0[i0 * NT + nc], U0[(i0 + 1) * NT + nc]);
            }
    }

    // ---- A producer: thread -> row tid>>1, 16 contiguous k (2x16B chunks)
    const int prow = tid >> 1;
    const int pc   = (tid & 1) * 2;                 // chunk base 0 or 2
    const float* gx = x + (long)(m0 + prow) * KT + k0 + pc * 8;
    const uint32_t sts0 = (uint32_t)prow * PITCH + (uint32_t)pc * 16;

    // ---- A consumer (ldmatrix): lane -> row/k-chunk
    const int lt = lane >> 3, lr = lane & 7;
    const uint32_t lbase = (uint32_t)(wm + (lt & 1) * 8 + lr) * PITCH
                         + (uint32_t)((lt >> 1) * 16);

    // ---- prologue ----
    float4 xr[4];
#pragma unroll
    for (int q = 0; q < 4; q++) xr[q] = *(const float4*)(gx + q * 4);
    {   // pack stage 0 -> slot 0
        uint4 v0, v1;
        v0.x = pkh2(xr[0].x, xr[0].y); v0.y = pkh2(xr[0].z, xr[0].w);
        v0.z = pkh2(xr[1].x, xr[1].y); v0.w = pkh2(xr[1].z, xr[1].w);
        v1.x = pkh2(xr[2].x, xr[2].y); v1.y = pkh2(xr[2].z, xr[2].w);
        v1.z = pkh2(xr[3].x, xr[3].y); v1.w = pkh2(xr[3].z, xr[3].w);
        *(uint4*)(smem + sts0)      = v0;
        *(uint4*)(smem + sts0 + 16) = v1;
    }
#pragma unroll
    for (int q = 0; q < 4; q++) xr[q] = *(const float4*)(gx + BK + q * 4);

    uint32_t p12h[4];
#pragma unroll
    for (int nf = 0; nf < 4; nf++) {
        const int nc = n0 + wn + nf * 8 + g;
        const float p = U2[(z * 8) * NT + nc] * U1[nc];
        p12h[nf] = pkh2(p, p);
    }
    __syncthreads();

    float acc[2][4][4];
#pragma unroll
    for (int mf = 0; mf < 2; mf++)
#pragma unroll
        for (int nf = 0; nf < 4; nf++)
#pragma unroll
            for (int i = 0; i < 4; i++) acc[mf][nf][i] = 0.0f;

    for (int s = 0; s < NS; s++) {
        // store stage s+1 (regs loaded at iter s-1) -> slot (s+1)%3
        if (s + 1 < NS) {
            char* sd = smem + ((s + 1) % 3) * SLOT_BYTES;
            uint4 v0, v1;
            v0.x = pkh2(xr[0].x, xr[0].y); v0.y = pkh2(xr[0].z, xr[0].w);
            v0.z = pkh2(xr[1].x, xr[1].y); v0.w = pkh2(xr[1].z, xr[1].w);
            v1.x = pkh2(xr[2].x, xr[2].y); v1.y = pkh2(xr[2].z, xr[2].w);
            v1.z = pkh2(xr[3].x, xr[3].y); v1.w = pkh2(xr[3].z, xr[3].w);
            *(uint4*)(sd + sts0)      = v0;
            *(uint4*)(sd + sts0 + 16) = v1;
        }
        // load stage s+2 into regs (one full stage of latency coverage)
        if (s + 2 < NS) {
            const float* gs = gx + (long)(s + 2) * BK;
#pragma unroll
            for (int q = 0; q < 4; q++) xr[q] = *(const float4*)(gs + q * 4);
        }
        // next-stage W scalars (L1/L2-resident U1, U2)
        float u1n[4], u2n[4];
        if (s + 1 < NS) {
            const int i1n = (s + 1) & 31;
            const int i2n = z * 8 + ((s + 1) >> 5);
#pragma unroll
            for (int nf = 0; nf < 4; nf++) {
                const int nc = n0 + wn + nf * 8 + g;
                u2n[nf] = U2[i2n * NT + nc];
                u1n[nf] = U1[i1n * NT + nc];
            }
        }

        __syncthreads();

        const uint32_t slotb = sb + (s % 3) * SLOT_BYTES;
#pragma unroll
        for (int ks = 0; ks < 2; ks++) {
            uint32_t a0[4], a1[4];
            ldm4(a0, slotb + lbase + ks * 32);
            ldm4(a1, slotb + lbase + ks * 32 + 16 * PITCH);
#pragma unroll
            for (int nf = 0; nf < 4; nf++) {
                const uint32_t b0 = hm2(p12h[nf], u0h[nf][ks][0]);
                const uint32_t b1 = hm2(p12h[nf], u0h[nf][ks][1]);
                mma16816(acc[0][nf], a0, b0, b1);
                mma16816(acc[1][nf], a1, b0, b1);
            }
        }

        if (s + 1 < NS) {
#pragma unroll
            for (int nf = 0; nf < 4; nf++) {
                const float p = u2n[nf] * u1n[nf];
                p12h[nf] = pkh2(p, p);
            }
        }
    }

    // ---- write split partials ----
    float* part = g_part + (long)z * MT * NT;
#pragma unroll
    for (int mf = 0; mf < 2; mf++) {
        const int mr = m0 + wm + mf * 16 + g;
#pragma unroll
        for (int nf = 0; nf < 4; nf++) {
            const int nc = n0 + wn + nf * 8 + tg * 2;
            float2 v0, v1;
            v0.x = acc[mf][nf][0]; v0.y = acc[mf][nf][1];
            v1.x = acc[mf][nf][2]; v1.y = acc[mf][nf][3];
            *(float2*)&part[(long)mr * NT + nc]       = v0;
            *(float2*)&part[(long)(mr + 8) * NT + nc] = v1;
        }
    }

    // ---- fused split-K reduction: last CTA per (m,n) tile sums partials ----
    __threadfence();
    __syncthreads();
    if (tid == 0) {
        const int tile = blockIdx.x * (NT / BN) + blockIdx.y;
        const int old = atomicAdd(&g_cnt[tile], 1);
        s_flag = (old == SPLITS - 1);
        if (s_flag) g_cnt[tile] = 0;            // reset for next graph replay
    }
    __syncthreads();
    if (s_flag) {
        __threadfence();
#pragma unroll
        for (int j = 0; j < (BM * BN / 4) / 256; j++) {   // 8 float4 / thread
            const int f   = tid + 256 * j;
            const int row = f >> 4;              // 16 float4 per 64-col row
            const int c4  = f & 15;
            const long off = (long)(m0 + row) * NT + n0 + c4 * 4;
            float4 sum = *(const float4*)(g_part + off);
#pragma unroll
            for (int zz = 1; zz < SPLITS; zz++) {
                const float4 v = *(const float4*)(g_part + (long)zz * MT * NT + off);
                sum.x += v.x; sum.y += v.y; sum.z += v.z; sum.w += v.w;
            }
            *(float4*)(out + off) = sum;
        }
    }
}

// ---------------------------------------------------------------------------
extern "C" void kernel_launch(void* const* d_in, const int* in_sizes, int n_in,
                              void* d_out, int out_size) {
    const float* x  = (const float*)d_in[0];
    const float* U0 = (const float*)d_in[1];
    const float* U1 = (const float*)d_in[2];
    const float* U2 = (const float*)d_in[3];
    float* out = (float*)d_out;

    static int smem_set = 0;
    if (!smem_set) {
        cudaFuncSetAttribute(gemm_kernel, cudaFuncAttributeMaxDynamicSharedMemorySize,
                             SMEM_BYTES);
        smem_set = 1;
    }

    dim3 grid(MT / BM, NT / BN, SPLITS);   // (16, 4, 4) = 256 CTAs, occ 2/SM
    gemm_kernel<<<grid, 256, SMEM_BYTES>>>(x, U0, U1, U2, out);
}